// round 1
// baseline (speedup 1.0000x reference)
#include <cuda_runtime.h>

#define NN 65536
#define DD 512
#define HH 256
#define KC 16
#define LV 3
#define CC 64
#define CK 1024   // CC*KC

// ---------------- device scratch (no allocations allowed) ----------------
__device__ float g_claccum[CC*DD];   // per-class accumulated lp (sum over levels)
__device__ int   g_seg[NN];          // combined (class, cluster) segment id per row
__device__ float g_means[CK*DD];
__device__ float g_cnt[CK];
__device__ float g_h[CK*DD];
__device__ float g_ref[CK*DD];
__device__ float g_lp[LV*CC*DD];

// ---------------- init: zero class accumulator ----------------
__global__ void init_kernel() {
    int i = blockIdx.x * blockDim.x + threadIdx.x;
    if (i < CC*DD) g_claccum[i] = 0.f;
}

// ---------------- fused cluster-head: hidden GEMM + logits + argmax ----------------
// Block = 64 rows. hidden tile [64 x 256] computed with BK=16 smem tiles,
// kept in smem, then logits [64 x 16] and argmax -> g_seg.
// A-tile load adds g_claccum[label] on the fly (current never materialized).
__global__ __launch_bounds__(256, 2) void assign_kernel(
    const float* __restrict__ X, const int* __restrict__ labels,
    const float* __restrict__ w1, const float* __restrict__ b1,
    const float* __restrict__ w2, const float* __restrict__ b2)
{
    extern __shared__ float sm[];
    float* hid = sm;                 // 64*256 = 16384 floats
    float* As  = sm + 16384;         // 64*17  = 1088
    float* Bs  = sm + 16384 + 1088;  // 16*256 = 4096
    float* w2s = sm + 16384;         // reuse As/Bs region (4096 floats)
    float* lg  = sm + 21568;         // 64*16  = 1024
    __shared__ int labs[64];

    int tid = threadIdx.x;
    int row0 = blockIdx.x * 64;
    if (tid < 64) labs[tid] = labels[row0 + tid];
    __syncthreads();

    int tx = tid & 15, ty = tid >> 4;
    float acc[4][16];
#pragma unroll
    for (int i = 0; i < 4; i++)
#pragma unroll
        for (int j = 0; j < 16; j++) acc[i][j] = 0.f;

    int ar = tid >> 2, ac = (tid & 3) << 2;
    const float* xrow  = X + (size_t)(row0 + ar) * DD;
    const float* clrow = g_claccum + (size_t)labs[ar] * DD;

    for (int kt = 0; kt < DD; kt += 16) {
        // A tile [64 x 16], stored As[row][k] with pad 17; add class accumulator
        float4 xa = *(const float4*)(xrow + kt + ac);
        float4 ca = *(const float4*)(clrow + kt + ac);
        As[ar*17 + ac + 0] = xa.x + ca.x;
        As[ar*17 + ac + 1] = xa.y + ca.y;
        As[ar*17 + ac + 2] = xa.z + ca.z;
        As[ar*17 + ac + 3] = xa.w + ca.w;
        // B tile [16 x 256]
#pragma unroll
        for (int q = 0; q < 4; q++) {
            int f  = q * 256 + tid;
            int br = f >> 6, bc = (f & 63) << 2;
            *(float4*)(Bs + br*256 + bc) = *(const float4*)(w1 + (size_t)(kt + br) * HH + bc);
        }
        __syncthreads();
#pragma unroll
        for (int kk = 0; kk < 16; kk++) {
            float av[4];
#pragma unroll
            for (int i = 0; i < 4; i++) av[i] = As[(ty*4 + i)*17 + kk];
            float bcol[16];
            *(float4*)&bcol[0]  = *(float4*)(Bs + kk*256 + tx*16 + 0);
            *(float4*)&bcol[4]  = *(float4*)(Bs + kk*256 + tx*16 + 4);
            *(float4*)&bcol[8]  = *(float4*)(Bs + kk*256 + tx*16 + 8);
            *(float4*)&bcol[12] = *(float4*)(Bs + kk*256 + tx*16 + 12);
#pragma unroll
            for (int i = 0; i < 4; i++)
#pragma unroll
                for (int j = 0; j < 16; j++) acc[i][j] += av[i] * bcol[j];
        }
        __syncthreads();
    }

    // bias + relu -> hid
#pragma unroll
    for (int i = 0; i < 4; i++) {
        int r = ty*4 + i;
#pragma unroll
        for (int j = 0; j < 16; j++) {
            int cidx = tx*16 + j;
            hid[r*256 + cidx] = fmaxf(acc[i][j] + b1[cidx], 0.f);
        }
    }
    __syncthreads();

    // load w2 [256 x 16] into the (now free) tile region
#pragma unroll
    for (int q = 0; q < 16; q++) { int f = q*256 + tid; w2s[f] = w2[f]; }
    __syncthreads();

    // logits: 64 rows x 16 clusters = 1024 tasks over 256 threads
#pragma unroll
    for (int t = 0; t < 4; t++) {
        int task = t*256 + tid;
        int r = task >> 4, k = task & 15;
        float a = b2[k];
        for (int j = 0; j < 256; j += 4) {
            float4 hv = *(float4*)(hid + r*256 + j);
            a += hv.x * w2s[(j+0)*16 + k];
            a += hv.y * w2s[(j+1)*16 + k];
            a += hv.z * w2s[(j+2)*16 + k];
            a += hv.w * w2s[(j+3)*16 + k];
        }
        lg[r*16 + k] = a;
    }
    __syncthreads();

    // argmax (strict > keeps first index, matching jnp.argmax)
    if (tid < 64) {
        float best = lg[tid*16]; int bi = 0;
#pragma unroll
        for (int k = 1; k < 16; k++) {
            float v = lg[tid*16 + k];
            if (v > best) { best = v; bi = k; }
        }
        g_seg[row0 + tid] = labs[tid]*KC + bi;
    }
}

// ---------------- deterministic per-segment mean (block = segment) ----------------
// Ballot-compaction keeps accumulation in global index order (no atomics).
// mean = (sum(X rows) + cnt * claccum[class]) / max(cnt, 1)
__global__ __launch_bounds__(512) void segsum_kernel(const float* __restrict__ X)
{
    __shared__ int idxbuf[8192];
    __shared__ int warpcnt[16];
    int tid = threadIdx.x, w = tid >> 5, lane = tid & 31;
    int myseg = blockIdx.x;

    float acc = 0.f;
    int total = 0;
    for (int c = 0; c < 8; c++) {
        int ccount = 0;
        for (int gph = 0; gph < 16; gph++) {
            int i = c*8192 + gph*512 + tid;
            bool m = (g_seg[i] == myseg);
            unsigned bal = __ballot_sync(0xffffffffu, m);
            if (lane == 0) warpcnt[w] = __popc(bal);
            __syncthreads();
            int pre = 0, gtot = 0;
#pragma unroll
            for (int ww = 0; ww < 16; ww++) {
                int cw = warpcnt[ww];
                if (ww < w) pre += cw;
                gtot += cw;
            }
            if (m) idxbuf[ccount + pre + __popc(bal & ((1u << lane) - 1u))] = i;
            ccount += gtot;
            __syncthreads();
        }
        // accumulate (thread = dim), 4-wide MLP
        int j = 0;
        for (; j + 4 <= ccount; j += 4) {
            int i0 = idxbuf[j], i1 = idxbuf[j+1], i2 = idxbuf[j+2], i3 = idxbuf[j+3];
            acc += X[(size_t)i0*DD + tid] + X[(size_t)i1*DD + tid]
                 + X[(size_t)i2*DD + tid] + X[(size_t)i3*DD + tid];
        }
        for (; j < ccount; j++) acc += X[(size_t)idxbuf[j]*DD + tid];
        total += ccount;
        __syncthreads();
    }

    int cls = myseg >> 4;
    float clv = g_claccum[cls*DD + tid];
    float mean = (acc + (float)total * clv) / fmaxf((float)total, 1.f);
    g_means[myseg*DD + tid] = mean;
    if (tid == 0) g_cnt[myseg] = (float)total;
}

// ---------------- generic tiled SGEMM: C[M,N] = A[M,K]@B[K,N] + bias ----------------
__global__ __launch_bounds__(256) void sgemm_bias(
    const float* __restrict__ A, const float* __restrict__ B,
    const float* __restrict__ bias, float* __restrict__ Cmat,
    int M, int Nout, int Kdim)
{
    __shared__ float As[64*17];
    __shared__ float Bs[16*65];
    int tid = threadIdx.x;
    int tx = tid & 15, ty = tid >> 4;
    int colBase = blockIdx.x * 64, rowBase = blockIdx.y * 64;
    float acc[4][4] = {};
    int ar = tid >> 2, ac = (tid & 3) << 2;
    int br = tid >> 4, bc = (tid & 15) << 2;

    for (int kt = 0; kt < Kdim; kt += 16) {
        float4 av = *(const float4*)(A + (size_t)(rowBase + ar)*Kdim + kt + ac);
        As[ar*17 + ac + 0] = av.x; As[ar*17 + ac + 1] = av.y;
        As[ar*17 + ac + 2] = av.z; As[ar*17 + ac + 3] = av.w;
        float4 bv = *(const float4*)(B + (size_t)(kt + br)*Nout + colBase + bc);
        Bs[br*65 + bc + 0] = bv.x; Bs[br*65 + bc + 1] = bv.y;
        Bs[br*65 + bc + 2] = bv.z; Bs[br*65 + bc + 3] = bv.w;
        __syncthreads();
#pragma unroll
        for (int kk = 0; kk < 16; kk++) {
            float a[4], b[4];
#pragma unroll
            for (int i = 0; i < 4; i++) a[i] = As[(ty*4 + i)*17 + kk];
#pragma unroll
            for (int j = 0; j < 4; j++) b[j] = Bs[kk*65 + tx*4 + j];
#pragma unroll
            for (int i = 0; i < 4; i++)
#pragma unroll
                for (int j = 0; j < 4; j++) acc[i][j] += a[i] * b[j];
        }
        __syncthreads();
    }
#pragma unroll
    for (int i = 0; i < 4; i++)
#pragma unroll
        for (int j = 0; j < 4; j++)
            Cmat[(size_t)(rowBase + ty*4 + i)*Nout + colBase + tx*4 + j] =
                acc[i][j] + bias[colBase + tx*4 + j];
}

// ---------------- LayerNorm + ReLU over rows of g_h ----------------
__global__ __launch_bounds__(512) void ln_relu_kernel(
    const float* __restrict__ gw, const float* __restrict__ bw)
{
    __shared__ float red[16];
    int tid = threadIdx.x, row = blockIdx.x;
    float x = g_h[(size_t)row*DD + tid];

    float s = x;
#pragma unroll
    for (int o = 16; o > 0; o >>= 1) s += __shfl_xor_sync(0xffffffffu, s, o);
    if ((tid & 31) == 0) red[tid >> 5] = s;
    __syncthreads();
    float tot = 0.f;
#pragma unroll
    for (int ww = 0; ww < 16; ww++) tot += red[ww];
    float m = tot * (1.f / 512.f);
    float d = x - m;
    float q = d * d;
    __syncthreads();
#pragma unroll
    for (int o = 16; o > 0; o >>= 1) q += __shfl_xor_sync(0xffffffffu, q, o);
    if ((tid & 31) == 0) red[tid >> 5] = q;
    __syncthreads();
    float tot2 = 0.f;
#pragma unroll
    for (int ww = 0; ww < 16; ww++) tot2 += red[ww];
    float v = tot2 * (1.f / 512.f);
    float y = d * rsqrtf(v + 1e-5f) * gw[tid] + bw[tid];
    g_h[(size_t)row*DD + tid] = fmaxf(y, 0.f);
}

// ---------------- level prototype: masked mean over non-empty clusters ----------------
__global__ __launch_bounds__(512) void lp_kernel(int l)
{
    int c = blockIdx.x, tid = threadIdx.x;
    float s = 0.f, net = 0.f;
#pragma unroll
    for (int k = 0; k < 16; k++) {
        float cn = g_cnt[c*16 + k];
        if (cn > 0.f) { s += g_ref[(size_t)(c*16 + k)*DD + tid]; net += 1.f; }
    }
    float lp = s / fmaxf(net, 1.f);
    g_lp[(size_t)l*CC*DD + c*DD + tid] = lp;
    g_claccum[c*DD + tid] += lp;
}

// ---------------- final combiner ----------------
__global__ __launch_bounds__(512) void combiner_kernel(
    const float* __restrict__ w1, const float* __restrict__ b1,
    const float* __restrict__ w2, const float* __restrict__ b2,
    float* __restrict__ out)
{
    __shared__ float comb[LV*DD];
    __shared__ float t1[DD];
    int c = blockIdx.x, tid = threadIdx.x;
    for (int j = tid; j < LV*DD; j += 512) {
        int lev = j >> 9, dd = j & 511;
        comb[j] = g_lp[(size_t)lev*CC*DD + c*DD + dd];
    }
    __syncthreads();
    float a = b1[tid];
    for (int i = 0; i < LV*DD; i += 8) {
#pragma unroll
        for (int u = 0; u < 8; u++) a += comb[i+u] * w1[(size_t)(i+u)*DD + tid];
    }
    t1[tid] = fmaxf(a, 0.f);
    __syncthreads();
    float a2 = b2[tid];
    for (int i = 0; i < DD; i += 8) {
#pragma unroll
        for (int u = 0; u < 8; u++) a2 += t1[i+u] * w2[(size_t)(i+u)*DD + tid];
    }
    out[c*DD + tid] = a2;
}

// ---------------- launcher ----------------
extern "C" void kernel_launch(void* const* d_in, const int* in_sizes, int n_in,
                              void* d_out, int out_size)
{
    const float* X      = (const float*)d_in[0];
    const int*   labels = (const int*)  d_in[1];
    const float* ch_w1  = (const float*)d_in[2];
    const float* ch_b1  = (const float*)d_in[3];
    const float* ch_w2  = (const float*)d_in[4];
    const float* ch_b2  = (const float*)d_in[5];
    const float* ref_w1 = (const float*)d_in[6];
    const float* ref_b1 = (const float*)d_in[7];
    const float* ln_g   = (const float*)d_in[8];
    const float* ln_b   = (const float*)d_in[9];
    const float* ref_w2 = (const float*)d_in[10];
    const float* ref_b2 = (const float*)d_in[11];
    const float* comb_w1 = (const float*)d_in[12];
    const float* comb_b1 = (const float*)d_in[13];
    const float* comb_w2 = (const float*)d_in[14];
    const float* comb_b2 = (const float*)d_in[15];
    float* out = (float*)d_out;

    const int SMEM_ASSIGN = 22592 * 4;  // 90368 B dynamic smem
    cudaFuncSetAttribute(assign_kernel, cudaFuncAttributeMaxDynamicSharedMemorySize, SMEM_ASSIGN);

    float *means_p, *h_p, *ref_p;
    cudaGetSymbolAddress((void**)&means_p, g_means);
    cudaGetSymbolAddress((void**)&h_p,     g_h);
    cudaGetSymbolAddress((void**)&ref_p,   g_ref);

    init_kernel<<<64, 512>>>();
    for (int l = 0; l < LV; l++) {
        assign_kernel<<<NN/64, 256, SMEM_ASSIGN>>>(
            X, labels,
            ch_w1 + (size_t)l*DD*HH, ch_b1 + (size_t)l*HH,
            ch_w2 + (size_t)l*HH*KC, ch_b2 + (size_t)l*KC);
        segsum_kernel<<<CK, 512>>>(X);
        sgemm_bias<<<dim3(DD/64, CK/64), 256>>>(
            means_p, ref_w1 + (size_t)l*DD*DD, ref_b1 + (size_t)l*DD, h_p, CK, DD, DD);
        ln_relu_kernel<<<CK, 512>>>(ln_g + (size_t)l*DD, ln_b + (size_t)l*DD);
        sgemm_bias<<<dim3(DD/64, CK/64), 256>>>(
            h_p, ref_w2 + (size_t)l*DD*DD, ref_b2 + (size_t)l*DD, ref_p, CK, DD, DD);
        lp_kernel<<<CC, 512>>>(l);
    }
    combiner_kernel<<<CC, 512>>>(comb_w1, comb_b1, comb_w2, comb_b2, out);
}